// round 5
// baseline (speedup 1.0000x reference)
#include <cuda_runtime.h>
#include <math_constants.h>
#include <cstdint>

// FilterDetection: score threshold + morphological opening (erode k=4 -> dilate k=4)
// cv2 semantics: erode offsets [-2,+1] (border +inf), dilate offsets [-1,+2]
// (eroded plane outside image = -inf).
//
// Register-pipeline kernel: each WARP owns a 128-col x 64-row strip in TWO
// images simultaneously (2-way ILP: independent pipelines fill each other's
// LDG/SHFL latency). van Herk factorization both axes. No smem, no syncs.

#define CHUNK  128   // columns per warp (32 lanes x float4)
#define RSTRIP 64    // output rows per warp
#define WARPS  4     // warps per CTA
#define ZSPLIT 16    // blockIdx.z images; each warp also does z+16

__device__ __forceinline__ float thr(float v) { return (v >= 0.5f) ? v : 0.0f; }

__global__ void score_thresh_kernel(const float* __restrict__ s,
                                    float* __restrict__ out, int n) {
    int i = blockIdx.x * blockDim.x + threadIdx.x;
    if (i < n) {
        float v = s[i];
        out[i] = (v >= 0.5f) ? v : 0.0f;
    }
}

struct Pipe {
    const float* img;
    float*       oimg;
    float4 hprev;  float hl, hr0, hr1;
    float4 pring[2]; float plr[2], pr0r[2], pr1r[2];
    float4 gprev;
    float4 sring[2];
};

__global__ __launch_bounds__(32 * WARPS, 4)
void open_kernel(const float* __restrict__ mask, float* __restrict__ out) {
    const int lane  = threadIdx.x;
    const int warp  = threadIdx.y;
    const int chunk = blockIdx.x;                       // 0..7
    const int c0    = chunk * CHUNK;
    const int r0    = (blockIdx.y * WARPS + warp) * RSTRIP;
    const int col   = c0 + lane * 4;

    const bool leftEdge  = (chunk == 0);
    const bool rightEdge = (chunk == 7);
    const float INF = CUDART_INF_F;

    Pipe P[2];
    P[0].img  = mask + (size_t)blockIdx.z * (1024u * 1024u);
    P[0].oimg = out  + (size_t)blockIdx.z * (1024u * 1024u);
    P[1].img  = mask + (size_t)(blockIdx.z + ZSPLIT) * (1024u * 1024u);
    P[1].oimg = out  + (size_t)(blockIdx.z + ZSPLIT) * (1024u * 1024u);

    auto step = [&](Pipe& p, int t, bool doP, bool doEV, bool doS, bool doOut)
        __attribute__((always_inline)) {
        const int ir  = r0 - 3 + t;
        const int par = t & 1;

        // ---- load input row (thresholded; OOB row -> +inf) ----
        float4 v;
        float xly, xlz, xlw, xrx, xry, xrz;
        xly = xlz = xlw = INF; xrx = xry = xrz = INF;
        if ((unsigned)ir < 1024u) {
            const float* rowp = p.img + (size_t)ir * 1024;
            float4 raw = *reinterpret_cast<const float4*>(rowp + col);
            v.x = thr(raw.x); v.y = thr(raw.y); v.z = thr(raw.z); v.w = thr(raw.w);
            if (lane == 0 && !leftEdge) {
                float4 b = *reinterpret_cast<const float4*>(rowp + c0 - 4);
                xly = thr(b.y); xlz = thr(b.z); xlw = thr(b.w);
            }
            if (lane == 31 && !rightEdge) {
                float4 b = *reinterpret_cast<const float4*>(rowp + c0 + CHUNK);
                xrx = thr(b.x); xry = thr(b.y); xrz = thr(b.z);
            }
        } else {
            v = make_float4(INF, INF, INF, INF);
        }

        // ---- horizontal erode: h_j = min(q_{j-2}, q_j), q_j = min(v_j, v_{j+1}) ----
        float vrx = __shfl_down_sync(0xffffffffu, v.x, 1);
        if (lane == 31) vrx = xrx;
        float4 q;
        q.x = fminf(v.x, v.y); q.y = fminf(v.y, v.z);
        q.z = fminf(v.z, v.w); q.w = fminf(v.w, vrx);
        float qpz = __shfl_up_sync(0xffffffffu, q.z, 1);
        float qpw = __shfl_up_sync(0xffffffffu, q.w, 1);
        if (lane == 0) { qpz = fminf(xlz, xlw); qpw = fminf(xlw, v.x); }
        float4 h;
        h.x = fminf(qpz, q.x); h.y = fminf(qpw, q.y);
        h.z = fminf(q.x, q.z); h.w = fminf(q.y, q.w);
        float hl  = fminf(fminf(xly, xlz), qpw);   // h @ col c0-1   (lane 0)
        float hr0 = fminf(q.z, fminf(xrx, xry));   // h @ col c0+128 (lane 31)
        float hr1 = fminf(q.w, fminf(xry, xrz));   // h @ col c0+129 (lane 31)

        if (doP) {
            float4 pn;
            pn.x = fminf(h.x, p.hprev.x); pn.y = fminf(h.y, p.hprev.y);
            pn.z = fminf(h.z, p.hprev.z); pn.w = fminf(h.w, p.hprev.w);
            float pln  = fminf(hl,  p.hl);
            float pr0n = fminf(hr0, p.hr0);
            float pr1n = fminf(hr1, p.hr1);

            if (doEV) {
                const int e = ir - 1;
                float4 ev; float evL, evR0, evR1;
                if ((unsigned)e < 1024u) {
                    float4 po = p.pring[par];
                    ev.x = fminf(po.x, pn.x); ev.y = fminf(po.y, pn.y);
                    ev.z = fminf(po.z, pn.z); ev.w = fminf(po.w, pn.w);
                    evL  = fminf(p.plr[par],  pln);
                    evR0 = fminf(p.pr0r[par], pr0n);
                    evR1 = fminf(p.pr1r[par], pr1n);
                } else {
                    ev = make_float4(-INF, -INF, -INF, -INF);
                    evL = evR0 = evR1 = -INF;
                }

                // horizontal dilate: g_j = max(r_j, r_{j+2}), r_j = max(ev_{j-1}, ev_j)
                float evwu = __shfl_up_sync(0xffffffffu, ev.w, 1);
                if (lane == 0) evwu = leftEdge ? -INF : evL;
                float4 r;
                r.x = fmaxf(evwu, ev.x); r.y = fmaxf(ev.x, ev.y);
                r.z = fmaxf(ev.y, ev.z); r.w = fmaxf(ev.z, ev.w);
                float rnx = __shfl_down_sync(0xffffffffu, r.x, 1);
                float rny = __shfl_down_sync(0xffffffffu, r.y, 1);
                if (lane == 31) {
                    float a0 = rightEdge ? -INF : evR0;
                    float a1 = rightEdge ? -INF : evR1;
                    rnx = fmaxf(ev.w, a0);
                    rny = fmaxf(a0, a1);
                }
                float4 g;
                g.x = fmaxf(r.x, r.z); g.y = fmaxf(r.y, r.w);
                g.z = fmaxf(r.z, rnx); g.w = fmaxf(r.w, rny);

                if (doS) {
                    float4 sn;
                    sn.x = fmaxf(g.x, p.gprev.x); sn.y = fmaxf(g.y, p.gprev.y);
                    sn.z = fmaxf(g.z, p.gprev.z); sn.w = fmaxf(g.w, p.gprev.w);
                    if (doOut) {
                        float4 so = p.sring[par];
                        float4 o4;
                        o4.x = fmaxf(so.x, sn.x); o4.y = fmaxf(so.y, sn.y);
                        o4.z = fmaxf(so.z, sn.z); o4.w = fmaxf(so.w, sn.w);
                        const int o = ir - 3;
                        *reinterpret_cast<float4*>(p.oimg + (size_t)o * 1024 + col) = o4;
                    }
                    p.sring[par] = sn;
                }
                p.gprev = g;
            }
            p.pring[par] = pn; p.plr[par] = pln;
            p.pr0r[par] = pr0n; p.pr1r[par] = pr1n;
        }
        p.hprev = h; p.hl = hl; p.hr0 = hr0; p.hr1 = hr1;
    };

    // pipeline prologue (peeled), both pipes interleaved per t
    step(P[0], 0, false, false, false, false);
    step(P[1], 0, false, false, false, false);
    step(P[0], 1, true,  false, false, false);
    step(P[1], 1, true,  false, false, false);
    step(P[0], 2, true,  false, false, false);
    step(P[1], 2, true,  false, false, false);
    step(P[0], 3, true,  true,  false, false);
    step(P[1], 3, true,  true,  false, false);
    step(P[0], 4, true,  true,  true,  false);
    step(P[1], 4, true,  true,  true,  false);
    step(P[0], 5, true,  true,  true,  false);
    step(P[1], 5, true,  true,  true,  false);
    // steady state: one output row per pipe per iteration
#pragma unroll 2
    for (int t = 6; t < RSTRIP + 6; ++t) {
        step(P[0], t, true, true, true, true);
        step(P[1], t, true, true, true, true);
    }
}

extern "C" void kernel_launch(void* const* d_in, const int* in_sizes, int n_in,
                              void* d_out, int out_size) {
    const float* score = (const float*)d_in[0];   // 32*1000
    const float* mask  = (const float*)d_in[1];   // 32*1024*1024
    float* out = (float*)d_out;

    const int n_score = in_sizes[0];              // 32000
    float* out_score = out;
    float* out_mask  = out + n_score;

    score_thresh_kernel<<<(n_score + 255) / 256, 256>>>(score, out_score, n_score);

    dim3 grid(1024 / CHUNK, 1024 / (RSTRIP * WARPS), ZSPLIT);   // (8, 4, 16)
    dim3 block(32, WARPS);
    open_kernel<<<grid, block>>>(mask, out_mask);
}

// round 8
// speedup vs baseline: 1.7012x; 1.7012x over previous
#include <cuda_runtime.h>
#include <math_constants.h>
#include <cstdint>

// FilterDetection: score threshold + morphological opening (erode k=4 -> dilate k=4)
// cv2 semantics: erode offsets [-2,+1] (border +inf), dilate offsets [-1,+2]
// (eroded plane outside image = -inf).
//
// Register-pipeline kernel: each WARP owns a 128-col x 64-row strip.
// van Herk factorization both axes; all shuffles depth-1 (operate on raw row /
// eroded row directly). Threshold applied once at output (commutes with
// min/max since it's monotone). Score threshold fused into the same kernel.

#define CHUNK  128   // columns per warp (32 lanes x float4)
#define RSTRIP 64    // output rows per warp
#define WARPS  4     // warps per CTA
#define N_SCORE 32000

__global__ __launch_bounds__(32 * WARPS, 8)
void open_kernel(const float* __restrict__ mask, float* __restrict__ out,
                 const float* __restrict__ score, float* __restrict__ out_score) {
    const int lane  = threadIdx.x;
    const int warp  = threadIdx.y;
    const int chunk = blockIdx.x;                       // 0..7
    const int c0    = chunk * CHUNK;
    const int r0    = (blockIdx.y * WARPS + warp) * RSTRIP;
    const int col   = c0 + lane * 4;
    const float* img  = mask + (size_t)blockIdx.z * (1024u * 1024u);
    float*       oimg = out  + (size_t)blockIdx.z * (1024u * 1024u);

    // ---- fused score threshold (independent work, first N_SCORE threads) ----
    {
        int gtid = (((blockIdx.z * gridDim.y + blockIdx.y) * gridDim.x + blockIdx.x)
                    * (32 * WARPS)) + warp * 32 + lane;
        if (gtid < N_SCORE) {
            float s = score[gtid];
            out_score[gtid] = (s >= 0.5f) ? s : 0.0f;
        }
    }

    const bool leftEdge  = (chunk == 0);
    const bool rightEdge = (chunk == 7);
    const float INF = CUDART_INF_F;

    // pipeline state (raw values; threshold deferred to output)
    float4 hprev;  float hlprev, hr0prev, hr1prev;
    float4 pring[2]; float plr[2], pr0r[2], pr1r[2];
    float4 gprev;
    float4 sring[2];

    auto step = [&](int t, bool doP, bool doEV, bool doS, bool doOut)
        __attribute__((always_inline)) {
        const int ir  = r0 - 3 + t;
        const int par = t & 1;

        // ---- load raw input row (+inf OOB) ----
        float4 v;
        float xly, xlz, xlw, xrx, xry, xrz;
        xly = xlz = xlw = INF; xrx = xry = xrz = INF;
        if ((unsigned)ir < 1024u) {
            const float* rowp = img + (size_t)ir * 1024;
            v = *reinterpret_cast<const float4*>(rowp + col);
            if (lane == 0 && !leftEdge) {
                float4 b = *reinterpret_cast<const float4*>(rowp + c0 - 4);
                xly = b.y; xlz = b.z; xlw = b.w;
            }
            if (lane == 31 && !rightEdge) {
                float4 b = *reinterpret_cast<const float4*>(rowp + c0 + CHUNK);
                xrx = b.x; xry = b.y; xrz = b.z;
            }
        } else {
            v = make_float4(INF, INF, INF, INF);
        }

        // ---- horizontal erode: h_j = min(v_{j-2..j+1}) (van Herk, depth-1 shfl) ----
        float vrx = __shfl_down_sync(0xffffffffu, v.x, 1);   // v.x of lane+1
        float vwu = __shfl_up_sync  (0xffffffffu, v.w, 1);   // v.w of lane-1
        if (lane == 31) vrx = xrx;
        if (lane == 0)  vwu = xlw;
        float4 q;
        q.x = fminf(v.x, v.y); q.y = fminf(v.y, v.z);
        q.z = fminf(v.z, v.w); q.w = fminf(v.w, vrx);
        float qpz = __shfl_up_sync(0xffffffffu, q.z, 1);     // q.z of lane-1
        if (lane == 0) qpz = fminf(xlz, xlw);
        float qpw = fminf(vwu, v.x);                         // q.w of lane-1
        float4 h;
        h.x = fminf(qpz, q.x); h.y = fminf(qpw, q.y);
        h.z = fminf(q.x, q.z); h.w = fminf(q.y, q.w);
        float hl  = fminf(fminf(xly, xlz), qpw);   // h @ col c0-1   (lane 0)
        float hr0 = fminf(q.z, fminf(xrx, xry));   // h @ col c0+128 (lane 31)
        float hr1 = fminf(q.w, fminf(xry, xrz));   // h @ col c0+129 (lane 31)

        if (doP) {
            // vertical erode pairwise
            float4 pn;
            pn.x = fminf(h.x, hprev.x); pn.y = fminf(h.y, hprev.y);
            pn.z = fminf(h.z, hprev.z); pn.w = fminf(h.w, hprev.w);
            float pln  = fminf(hl,  hlprev);
            float pr0n = fminf(hr0, hr0prev);
            float pr1n = fminf(hr1, hr1prev);

            if (doEV) {
                const int e = ir - 1;
                float4 ev; float evL, evR0, evR1;
                if ((unsigned)e < 1024u) {
                    float4 po = pring[par];
                    ev.x = fminf(po.x, pn.x); ev.y = fminf(po.y, pn.y);
                    ev.z = fminf(po.z, pn.z); ev.w = fminf(po.w, pn.w);
                    evL  = leftEdge  ? -INF : fminf(plr[par],  pln);
                    evR0 = rightEdge ? -INF : fminf(pr0r[par], pr0n);
                    evR1 = rightEdge ? -INF : fminf(pr1r[par], pr1n);
                } else {
                    ev = make_float4(-INF, -INF, -INF, -INF);
                    evL = evR0 = evR1 = -INF;
                }

                // horizontal dilate: g_j = max(ev_{j-1..j+2}) (depth-1 shfl on ev)
                float evwu = __shfl_up_sync  (0xffffffffu, ev.w, 1);
                float evxd = __shfl_down_sync(0xffffffffu, ev.x, 1);
                float evyd = __shfl_down_sync(0xffffffffu, ev.y, 1);
                if (lane == 0)  evwu = evL;
                if (lane == 31) { evxd = evR0; evyd = evR1; }
                float4 r;
                r.x = fmaxf(evwu, ev.x); r.y = fmaxf(ev.x, ev.y);
                r.z = fmaxf(ev.y, ev.z); r.w = fmaxf(ev.z, ev.w);
                float rnx = fmaxf(ev.w, evxd);
                float rny = fmaxf(evxd, evyd);
                float4 g;
                g.x = fmaxf(r.x, r.z); g.y = fmaxf(r.y, r.w);
                g.z = fmaxf(r.z, rnx); g.w = fmaxf(r.w, rny);

                if (doS) {
                    // vertical dilate pairwise
                    float4 sn;
                    sn.x = fmaxf(g.x, gprev.x); sn.y = fmaxf(g.y, gprev.y);
                    sn.z = fmaxf(g.z, gprev.z); sn.w = fmaxf(g.w, gprev.w);
                    if (doOut) {
                        float4 so = sring[par];
                        float4 o4;
                        o4.x = fmaxf(so.x, sn.x); o4.y = fmaxf(so.y, sn.y);
                        o4.z = fmaxf(so.z, sn.z); o4.w = fmaxf(so.w, sn.w);
                        // threshold (monotone => commutes with opening)
                        o4.x = (o4.x >= 0.5f) ? o4.x : 0.0f;
                        o4.y = (o4.y >= 0.5f) ? o4.y : 0.0f;
                        o4.z = (o4.z >= 0.5f) ? o4.z : 0.0f;
                        o4.w = (o4.w >= 0.5f) ? o4.w : 0.0f;
                        const int o = ir - 3;
                        *reinterpret_cast<float4*>(oimg + (size_t)o * 1024 + col) = o4;
                    }
                    sring[par] = sn;
                }
                gprev = g;
            }
            pring[par] = pn; plr[par] = pln;
            pr0r[par] = pr0n; pr1r[par] = pr1n;
        }
        hprev = h; hlprev = hl; hr0prev = hr0; hr1prev = hr1;
    };

    // pipeline prologue (peeled)
    step(0, false, false, false, false);
    step(1, true,  false, false, false);
    step(2, true,  false, false, false);
    step(3, true,  true,  false, false);
    step(4, true,  true,  true,  false);
    step(5, true,  true,  true,  false);
    // steady state: one output row per iteration
#pragma unroll 4
    for (int t = 6; t < RSTRIP + 6; ++t) {
        step(t, true, true, true, true);
    }
}

extern "C" void kernel_launch(void* const* d_in, const int* in_sizes, int n_in,
                              void* d_out, int out_size) {
    const float* score = (const float*)d_in[0];   // 32*1000
    const float* mask  = (const float*)d_in[1];   // 32*1024*1024
    float* out = (float*)d_out;

    float* out_score = out;
    float* out_mask  = out + N_SCORE;

    dim3 grid(1024 / CHUNK, 1024 / (RSTRIP * WARPS), 32);   // (8, 4, 32) = 1024 CTAs
    dim3 block(32, WARPS);
    open_kernel<<<grid, block>>>(mask, out_mask, score, out_score);
}

// round 10
// speedup vs baseline: 2.0032x; 1.1775x over previous
#include <cuda_runtime.h>
#include <math_constants.h>
#include <cstdint>

// FilterDetection: score threshold + morphological opening (erode k=4 -> dilate k=4)
// cv2 semantics: erode offsets [-2,+1] (border +inf), dilate offsets [-1,+2]
// (eroded plane outside image = -inf).
//
// Register-pipeline kernel, R3 geometry (proven best): each WARP owns a
// 128-col x 64-row strip; 8 warps/CTA, 512 CTAs. ALL loads are
// unconditional (clamped addresses + selects, no branches in the loop) so
// ptxas batches 8 LDG.128 per unroll-4 group -> MLP 8 instead of ~1.

#define CHUNK  128   // columns per warp (32 lanes x float4)
#define RSTRIP 64    // output rows per warp
#define WARPS  8     // warps per CTA
#define N_SCORE 32000

__global__ __launch_bounds__(32 * WARPS, 4)
void open_kernel(const float* __restrict__ mask, float* __restrict__ out,
                 const float* __restrict__ score, float* __restrict__ out_score) {
    const int lane  = threadIdx.x;
    const int warp  = threadIdx.y;
    const int chunk = blockIdx.x;                       // 0..7
    const int c0    = chunk * CHUNK;
    const int r0    = (blockIdx.y * WARPS + warp) * RSTRIP;
    const int col   = c0 + lane * 4;
    const float* img  = mask + (size_t)blockIdx.z * (1024u * 1024u);
    float*       oimg = out  + (size_t)blockIdx.z * (1024u * 1024u);

    // ---- fused score threshold (independent work) ----
    {
        int gtid = (((blockIdx.z * gridDim.y + blockIdx.y) * gridDim.x + blockIdx.x)
                    * (32 * WARPS)) + warp * 32 + lane;
        if (gtid < N_SCORE) {
            float s = score[gtid];
            out_score[gtid] = (s >= 0.5f) ? s : 0.0f;
        }
    }

    const bool leftEdge  = (chunk == 0);
    const bool rightEdge = (chunk == 7);
    const float INF = CUDART_INF_F;

    // Loop-invariant halo setup: one extra LDG.128 per step, per-lane address.
    // Lane 0 fetches cols c0-4..c0-1, lane 31 fetches c0+128..c0+131,
    // other lanes harmlessly refetch their own word (same sectors).
    const bool pL = (lane == 0)  && !leftEdge;
    const bool pR = (lane == 31) && !rightEdge;
    int haloCol = col;
    if (pL) haloCol = c0 - 4;
    if (pR) haloCol = c0 + CHUNK;

    // pipeline state
    float4 hprev;  float hlprev, hr0prev, hr1prev;
    float4 pring[2]; float plr[2], pr0r[2], pr1r[2];
    float4 gprev;
    float4 sring[2];

    auto step = [&](int t, bool doP, bool doEV, bool doS, bool doOut)
        __attribute__((always_inline)) {
        const int ir  = r0 - 3 + t;
        const int par = t & 1;
        const bool rok = ((unsigned)ir < 1024u);
        const int irc = min(max(ir, 0), 1023);
        const float* rowp = img + (size_t)irc * 1024;

        // ---- unconditional loads (clamped addresses), selects afterwards ----
        float4 vr = *reinterpret_cast<const float4*>(rowp + col);
        float4 hb = *reinterpret_cast<const float4*>(rowp + haloCol);
        float4 v;
        v.x = rok ? vr.x : INF; v.y = rok ? vr.y : INF;
        v.z = rok ? vr.z : INF; v.w = rok ? vr.w : INF;
        const bool okL = pL && rok, okR = pR && rok;
        float xly = okL ? hb.y : INF, xlz = okL ? hb.z : INF, xlw = okL ? hb.w : INF;
        float xrx = okR ? hb.x : INF, xry = okR ? hb.y : INF, xrz = okR ? hb.z : INF;

        // ---- horizontal erode: h_j = min(v_{j-2..j+1}) (van Herk) ----
        float vrx = __shfl_down_sync(0xffffffffu, v.x, 1);
        float vwu = __shfl_up_sync  (0xffffffffu, v.w, 1);
        if (lane == 31) vrx = xrx;
        if (lane == 0)  vwu = xlw;
        float4 q;
        q.x = fminf(v.x, v.y); q.y = fminf(v.y, v.z);
        q.z = fminf(v.z, v.w); q.w = fminf(v.w, vrx);
        float qpz = __shfl_up_sync(0xffffffffu, q.z, 1);
        if (lane == 0) qpz = fminf(xlz, xlw);
        float qpw = fminf(vwu, v.x);                      // q.w of lane-1
        float4 h;
        h.x = fminf(qpz, q.x); h.y = fminf(qpw, q.y);
        h.z = fminf(q.x, q.z); h.w = fminf(q.y, q.w);
        float hl  = fminf(fminf(xly, xlz), qpw);   // h @ col c0-1   (lane 0)
        float hr0 = fminf(q.z, fminf(xrx, xry));   // h @ col c0+128 (lane 31)
        float hr1 = fminf(q.w, fminf(xry, xrz));   // h @ col c0+129 (lane 31)

        if (doP) {
            // vertical erode pairwise
            float4 pn;
            pn.x = fminf(h.x, hprev.x); pn.y = fminf(h.y, hprev.y);
            pn.z = fminf(h.z, hprev.z); pn.w = fminf(h.w, hprev.w);
            float pln  = fminf(hl,  hlprev);
            float pr0n = fminf(hr0, hr0prev);
            float pr1n = fminf(hr1, hr1prev);

            if (doEV) {
                const int e = ir - 1;
                const bool eok = ((unsigned)e < 1024u);
                float4 po = pring[par];
                float4 ev;
                ev.x = eok ? fminf(po.x, pn.x) : -INF;
                ev.y = eok ? fminf(po.y, pn.y) : -INF;
                ev.z = eok ? fminf(po.z, pn.z) : -INF;
                ev.w = eok ? fminf(po.w, pn.w) : -INF;
                float evL  = (eok && !leftEdge)  ? fminf(plr[par],  pln)  : -INF;
                float evR0 = (eok && !rightEdge) ? fminf(pr0r[par], pr0n) : -INF;
                float evR1 = (eok && !rightEdge) ? fminf(pr1r[par], pr1n) : -INF;

                // horizontal dilate: g_j = max(ev_{j-1..j+2})
                float evwu = __shfl_up_sync  (0xffffffffu, ev.w, 1);
                float evxd = __shfl_down_sync(0xffffffffu, ev.x, 1);
                float evyd = __shfl_down_sync(0xffffffffu, ev.y, 1);
                if (lane == 0)  evwu = evL;
                if (lane == 31) { evxd = evR0; evyd = evR1; }
                float4 r;
                r.x = fmaxf(evwu, ev.x); r.y = fmaxf(ev.x, ev.y);
                r.z = fmaxf(ev.y, ev.z); r.w = fmaxf(ev.z, ev.w);
                float rnx = fmaxf(ev.w, evxd);
                float rny = fmaxf(evxd, evyd);
                float4 g;
                g.x = fmaxf(r.x, r.z); g.y = fmaxf(r.y, r.w);
                g.z = fmaxf(r.z, rnx); g.w = fmaxf(r.w, rny);

                if (doS) {
                    // vertical dilate pairwise
                    float4 sn;
                    sn.x = fmaxf(g.x, gprev.x); sn.y = fmaxf(g.y, gprev.y);
                    sn.z = fmaxf(g.z, gprev.z); sn.w = fmaxf(g.w, gprev.w);
                    if (doOut) {
                        float4 so = sring[par];
                        float4 o4;
                        o4.x = fmaxf(so.x, sn.x); o4.y = fmaxf(so.y, sn.y);
                        o4.z = fmaxf(so.z, sn.z); o4.w = fmaxf(so.w, sn.w);
                        // threshold (monotone => commutes with opening)
                        o4.x = (o4.x >= 0.5f) ? o4.x : 0.0f;
                        o4.y = (o4.y >= 0.5f) ? o4.y : 0.0f;
                        o4.z = (o4.z >= 0.5f) ? o4.z : 0.0f;
                        o4.w = (o4.w >= 0.5f) ? o4.w : 0.0f;
                        const int o = ir - 3;
                        *reinterpret_cast<float4*>(oimg + (size_t)o * 1024 + col) = o4;
                    }
                    sring[par] = sn;
                }
                gprev = g;
            }
            pring[par] = pn; plr[par] = pln;
            pr0r[par] = pr0n; pr1r[par] = pr1n;
        }
        hprev = h; hlprev = hl; hr0prev = hr0; hr1prev = hr1;
    };

    // pipeline prologue (peeled)
    step(0, false, false, false, false);
    step(1, true,  false, false, false);
    step(2, true,  false, false, false);
    step(3, true,  true,  false, false);
    step(4, true,  true,  true,  false);
    step(5, true,  true,  true,  false);
    // steady state: one output row per iteration
#pragma unroll 4
    for (int t = 6; t < RSTRIP + 6; ++t) {
        step(t, true, true, true, true);
    }
}

extern "C" void kernel_launch(void* const* d_in, const int* in_sizes, int n_in,
                              void* d_out, int out_size) {
    const float* score = (const float*)d_in[0];   // 32*1000
    const float* mask  = (const float*)d_in[1];   // 32*1024*1024
    float* out = (float*)d_out;

    float* out_score = out;
    float* out_mask  = out + N_SCORE;

    dim3 grid(1024 / CHUNK, 1024 / (RSTRIP * WARPS), 32);   // (8, 2, 32) = 512 CTAs
    dim3 block(32, WARPS);
    open_kernel<<<grid, block>>>(mask, out_mask, score, out_score);
}

// round 11
// speedup vs baseline: 2.0658x; 1.0312x over previous
#include <cuda_runtime.h>
#include <math_constants.h>
#include <cstdint>

// FilterDetection: score threshold + morphological opening (erode k=4 -> dilate k=4)
// cv2 semantics: erode offsets [-2,+1] (border +inf), dilate offsets [-1,+2]
// (eroded plane outside image = -inf).
//
// Register-pipeline kernel, R3 geometry: each WARP owns a 128-col x 64-row
// strip; 8 warps/CTA, 512 CTAs. Branchless loads. This round: the steady loop
// is split into an interior section (t=6..65, provably in-bounds for all
// strips -> no clamps/selects, unroll 8 for 16-deep load batching) and a
// 4-step checked tail.

#define CHUNK  128   // columns per warp (32 lanes x float4)
#define RSTRIP 64    // output rows per warp
#define WARPS  8     // warps per CTA
#define N_SCORE 32000

__global__ __launch_bounds__(32 * WARPS, 4)
void open_kernel(const float* __restrict__ mask, float* __restrict__ out,
                 const float* __restrict__ score, float* __restrict__ out_score) {
    const int lane  = threadIdx.x;
    const int warp  = threadIdx.y;
    const int chunk = blockIdx.x;                       // 0..7
    const int c0    = chunk * CHUNK;
    const int r0    = (blockIdx.y * WARPS + warp) * RSTRIP;
    const int col   = c0 + lane * 4;
    const float* img  = mask + (size_t)blockIdx.z * (1024u * 1024u);
    float*       oimg = out  + (size_t)blockIdx.z * (1024u * 1024u);

    // ---- fused score threshold (independent work) ----
    {
        int gtid = (((blockIdx.z * gridDim.y + blockIdx.y) * gridDim.x + blockIdx.x)
                    * (32 * WARPS)) + warp * 32 + lane;
        if (gtid < N_SCORE) {
            float s = score[gtid];
            out_score[gtid] = (s >= 0.5f) ? s : 0.0f;
        }
    }

    const bool leftEdge  = (chunk == 0);
    const bool rightEdge = (chunk == 7);
    const float INF = CUDART_INF_F;

    // Loop-invariant halo address: lane 0 fetches cols c0-4..c0-1, lane 31
    // fetches c0+128..c0+131, interior lanes harmlessly refetch their word.
    const bool pL = (lane == 0)  && !leftEdge;
    const bool pR = (lane == 31) && !rightEdge;
    int haloCol = col;
    if (pL) haloCol = c0 - 4;
    if (pR) haloCol = c0 + CHUNK;

    // pipeline state
    float4 hprev;  float hlprev, hr0prev, hr1prev;
    float4 pring[2]; float plr[2], pr0r[2], pr1r[2];
    float4 gprev;
    float4 sring[2];

    // interior=true: ir and ir-1 are statically known in-bounds (no checks).
    auto step = [&](int t, bool doP, bool doEV, bool doS, bool doOut,
                    bool interior) __attribute__((always_inline)) {
        const int ir  = r0 - 3 + t;
        const int par = t & 1;
        const bool rok = interior || ((unsigned)ir < 1024u);
        const int irc = interior ? ir : min(max(ir, 0), 1023);
        const float* rowp = img + (size_t)irc * 1024;

        // ---- unconditional loads; selects only in non-interior steps ----
        float4 vr = *reinterpret_cast<const float4*>(rowp + col);
        float4 hb = *reinterpret_cast<const float4*>(rowp + haloCol);
        float4 v;
        if (interior) {
            v = vr;
        } else {
            v.x = rok ? vr.x : INF; v.y = rok ? vr.y : INF;
            v.z = rok ? vr.z : INF; v.w = rok ? vr.w : INF;
        }
        const bool okL = interior ? pL : (pL && rok);
        const bool okR = interior ? pR : (pR && rok);
        float xly = okL ? hb.y : INF, xlz = okL ? hb.z : INF, xlw = okL ? hb.w : INF;
        float xrx = okR ? hb.x : INF, xry = okR ? hb.y : INF, xrz = okR ? hb.z : INF;

        // ---- horizontal erode: h_j = min(v_{j-2..j+1}) (van Herk) ----
        float vrx = __shfl_down_sync(0xffffffffu, v.x, 1);
        float vwu = __shfl_up_sync  (0xffffffffu, v.w, 1);
        if (lane == 31) vrx = xrx;
        if (lane == 0)  vwu = xlw;
        float4 q;
        q.x = fminf(v.x, v.y); q.y = fminf(v.y, v.z);
        q.z = fminf(v.z, v.w); q.w = fminf(v.w, vrx);
        float qpz = __shfl_up_sync(0xffffffffu, q.z, 1);
        if (lane == 0) qpz = fminf(xlz, xlw);
        float qpw = fminf(vwu, v.x);                      // q.w of lane-1
        float4 h;
        h.x = fminf(qpz, q.x); h.y = fminf(qpw, q.y);
        h.z = fminf(q.x, q.z); h.w = fminf(q.y, q.w);
        float hl  = fminf(fminf(xly, xlz), qpw);   // h @ col c0-1   (lane 0)
        float hr0 = fminf(q.z, fminf(xrx, xry));   // h @ col c0+128 (lane 31)
        float hr1 = fminf(q.w, fminf(xry, xrz));   // h @ col c0+129 (lane 31)

        if (doP) {
            // vertical erode pairwise
            float4 pn;
            pn.x = fminf(h.x, hprev.x); pn.y = fminf(h.y, hprev.y);
            pn.z = fminf(h.z, hprev.z); pn.w = fminf(h.w, hprev.w);
            float pln  = fminf(hl,  hlprev);
            float pr0n = fminf(hr0, hr0prev);
            float pr1n = fminf(hr1, hr1prev);

            if (doEV) {
                const int e = ir - 1;
                const bool eok = interior || ((unsigned)e < 1024u);
                float4 po = pring[par];
                float4 ev;
                if (interior) {
                    ev.x = fminf(po.x, pn.x); ev.y = fminf(po.y, pn.y);
                    ev.z = fminf(po.z, pn.z); ev.w = fminf(po.w, pn.w);
                } else {
                    ev.x = eok ? fminf(po.x, pn.x) : -INF;
                    ev.y = eok ? fminf(po.y, pn.y) : -INF;
                    ev.z = eok ? fminf(po.z, pn.z) : -INF;
                    ev.w = eok ? fminf(po.w, pn.w) : -INF;
                }
                float evL  = (eok && !leftEdge)  ? fminf(plr[par],  pln)  : -INF;
                float evR0 = (eok && !rightEdge) ? fminf(pr0r[par], pr0n) : -INF;
                float evR1 = (eok && !rightEdge) ? fminf(pr1r[par], pr1n) : -INF;

                // horizontal dilate: g_j = max(ev_{j-1..j+2})
                float evwu = __shfl_up_sync  (0xffffffffu, ev.w, 1);
                float evxd = __shfl_down_sync(0xffffffffu, ev.x, 1);
                float evyd = __shfl_down_sync(0xffffffffu, ev.y, 1);
                if (lane == 0)  evwu = evL;
                if (lane == 31) { evxd = evR0; evyd = evR1; }
                float4 r;
                r.x = fmaxf(evwu, ev.x); r.y = fmaxf(ev.x, ev.y);
                r.z = fmaxf(ev.y, ev.z); r.w = fmaxf(ev.z, ev.w);
                float rnx = fmaxf(ev.w, evxd);
                float rny = fmaxf(evxd, evyd);
                float4 g;
                g.x = fmaxf(r.x, r.z); g.y = fmaxf(r.y, r.w);
                g.z = fmaxf(r.z, rnx); g.w = fmaxf(r.w, rny);

                if (doS) {
                    // vertical dilate pairwise
                    float4 sn;
                    sn.x = fmaxf(g.x, gprev.x); sn.y = fmaxf(g.y, gprev.y);
                    sn.z = fmaxf(g.z, gprev.z); sn.w = fmaxf(g.w, gprev.w);
                    if (doOut) {
                        float4 so = sring[par];
                        float4 o4;
                        o4.x = fmaxf(so.x, sn.x); o4.y = fmaxf(so.y, sn.y);
                        o4.z = fmaxf(so.z, sn.z); o4.w = fmaxf(so.w, sn.w);
                        // threshold (monotone => commutes with opening)
                        o4.x = (o4.x >= 0.5f) ? o4.x : 0.0f;
                        o4.y = (o4.y >= 0.5f) ? o4.y : 0.0f;
                        o4.z = (o4.z >= 0.5f) ? o4.z : 0.0f;
                        o4.w = (o4.w >= 0.5f) ? o4.w : 0.0f;
                        const int o = ir - 3;
                        *reinterpret_cast<float4*>(oimg + (size_t)o * 1024 + col) = o4;
                    }
                    sring[par] = sn;
                }
                gprev = g;
            }
            pring[par] = pn; plr[par] = pln;
            pr0r[par] = pr0n; pr1r[par] = pr1n;
        }
        hprev = h; hlprev = hl; hr0prev = hr0; hr1prev = hr1;
    };

    // pipeline prologue (peeled, checked)
    step(0, false, false, false, false, false);
    step(1, true,  false, false, false, false);
    step(2, true,  false, false, false, false);
    step(3, true,  true,  false, false, false);
    step(4, true,  true,  true,  false, false);
    step(5, true,  true,  true,  false, false);

    // interior steady state: t in [6,65] -> ir in [r0+3, r0+62] subset [3,1022]
    // for every strip (r0 <= 960): no bounds logic at all.
#pragma unroll 8
    for (int t = 6; t < 66; ++t) {
        step(t, true, true, true, true, true);
    }
    // checked tail (bottom strips run past row 1023 here)
#pragma unroll
    for (int t = 66; t < RSTRIP + 6; ++t) {
        step(t, true, true, true, true, false);
    }
}

extern "C" void kernel_launch(void* const* d_in, const int* in_sizes, int n_in,
                              void* d_out, int out_size) {
    const float* score = (const float*)d_in[0];   // 32*1000
    const float* mask  = (const float*)d_in[1];   // 32*1024*1024
    float* out = (float*)d_out;

    float* out_score = out;
    float* out_mask  = out + N_SCORE;

    dim3 grid(1024 / CHUNK, 1024 / (RSTRIP * WARPS), 32);   // (8, 2, 32) = 512 CTAs
    dim3 block(32, WARPS);
    open_kernel<<<grid, block>>>(mask, out_mask, score, out_score);
}